// round 3
// baseline (speedup 1.0000x reference)
#include <cuda_runtime.h>
#include <cuda_fp16.h>
#include <cuda_bf16.h>

// ---- physical constants (double-precision derived, matching reference) ----
#define KEHALF      7.199822675975274f
#define CUTON_F     2.5f
#define CUTOFF_F    7.5f
#define LRCUT_F     10.0f
#define CUTON16_F   2328306.4365386963f
#define CUT_RCONST  0.009999999997526174f
#define CUT_CONST   0.19999999999608f
#define INV_RANGE   0.2f
#define INV_LR2     0.01f
#define TWO_OVER_LR 0.2f

#define MAX_N 102400
#define MAX_M 2048
#define NSLOT 64

// i-side packed table: (q[i] fp32, idx_m[i]) -> ONE 8B gather per edge on L1tex
__device__ float2 d_qm[MAX_N];
// slot-strided global scratch: reduction goes here via fire-and-forget RED
__device__ float  d_scratch[MAX_M * NSLOT];

__global__ void prep_kernel(const float* __restrict__ q,
                            const int* __restrict__ idx_m,
                            int N, float* __restrict__ out, int M) {
    int stride = gridDim.x * blockDim.x;
    int tid = blockIdx.x * blockDim.x + threadIdx.x;
    for (int i = tid; i < N; i += stride)
        d_qm[i] = make_float2(q[i], __int_as_float(idx_m[i]));
    for (int i = tid; i < M; i += stride)
        out[i] = 0.0f;
    for (int i = tid; i < MAX_M * NSLOT; i += stride)
        d_scratch[i] = 0.0f;
}

__device__ __forceinline__ float edge_energy(float x, float y, float z,
                                             float qi, float qj) {
    float s  = fmaf(x, x, fmaf(y, y, z * z));   // d^2
    float rd = rsqrtf(s);                       // 1/d
    float d  = s * rd;                          // d
    float fac = KEHALF * qi * qj;

    float f;
    if (d >= CUTOFF_F) {
        f = 0.0f;
    } else if (d <= CUTON_F) {
        f = 1.0f;
    } else {
        float t = (CUTOFF_F - d) * INV_RANGE;
        float g = __fdividef(1.0f, t) - __fdividef(1.0f, 1.0f - t);
        f = __fdividef(1.0f, 1.0f + __expf(g));
    }

    float d4  = s * s;
    float d8  = d4 * d4;
    float d16 = d8 * d8;
    float p   = exp2f(-0.0625f * __log2f(d16 + CUTON16_F));

    float omf    = 1.0f - f;
    float damped = fmaf(omf * CUT_RCONST, d, p - CUT_CONST);
    float coul   = (d < LRCUT_F) ? (rd + fmaf(d, INV_LR2, -TWO_OVER_LR)) : 0.0f;
    return fac * fmaf(f, damped, omf * coul);
}

// Pipe specialization:
//   L1tex : streams (coalesced) + i-side packed gather (1 wavefront-set/edge)
//   smem  : j-side fp16 q table (random LDS, ~4-conflict)
//   LTS   : fire-and-forget RED into slot-strided scratch (no warp blocking)
__global__ __launch_bounds__(1024, 1)
void energy_kernel(const float4* __restrict__ r4,
                   const float*  __restrict__ q,
                   const int4*   __restrict__ ii4,
                   const int4*   __restrict__ jj4,
                   const float*  __restrict__ r_scalar,
                   const int*    __restrict__ idx_i,
                   const int*    __restrict__ idx_j,
                   int N, int P) {
    extern __shared__ __half qtab[];

    // stage q -> fp16 shared table (vectorized, coalesced)
    const float2* q2  = (const float2*)q;
    __half2*      qt2 = (__half2*)qtab;
    for (int i = threadIdx.x; i < (N >> 1); i += blockDim.x)
        qt2[i] = __float22half2_rn(q2[i]);
    if ((N & 1) && threadIdx.x == 0)
        qtab[N - 1] = __float2half_rn(q[N - 1]);
    __syncthreads();

    int gwarp = blockIdx.x * (blockDim.x >> 5) + (threadIdx.x >> 5);
    int slot  = gwarp & (NSLOT - 1);

    int gid    = blockIdx.x * blockDim.x + threadIdx.x;
    int stride = gridDim.x * blockDim.x;
    int P4 = P >> 2;

    for (int g = gid; g < P4; g += stride) {
        // coalesced streams, evict-first (one-pass data; keep d_qm hot in L2)
        float4 a = __ldcs(&r4[3 * g + 0]);
        float4 b = __ldcs(&r4[3 * g + 1]);
        float4 c = __ldcs(&r4[3 * g + 2]);
        int4 ii = __ldcs(&ii4[g]);
        int4 jj = __ldcs(&jj4[g]);

        // i-side: 4 independent 8B gathers (L1tex) -> MLP
        float2 m0 = __ldg(&((const float2*)d_qm)[ii.x]);
        float2 m1 = __ldg(&((const float2*)d_qm)[ii.y]);
        float2 m2 = __ldg(&((const float2*)d_qm)[ii.z]);
        float2 m3 = __ldg(&((const float2*)d_qm)[ii.w]);
        // j-side: shared-memory crossbar
        float qj0 = __half2float(qtab[jj.x]);
        float qj1 = __half2float(qtab[jj.y]);
        float qj2 = __half2float(qtab[jj.z]);
        float qj3 = __half2float(qtab[jj.w]);

        float e0 = edge_energy(a.x, a.y, a.z, m0.x, qj0);
        float e1 = edge_energy(a.w, b.x, b.y, m1.x, qj1);
        float e2 = edge_energy(b.z, b.w, c.x, m2.x, qj2);
        float e3 = edge_energy(c.y, c.z, c.w, m3.x, qj3);

        // fire-and-forget reduction (RED, return unused) into strided scratch
        atomicAdd(&d_scratch[__float_as_int(m0.y) * NSLOT + slot], e0);
        atomicAdd(&d_scratch[__float_as_int(m1.y) * NSLOT + slot], e1);
        atomicAdd(&d_scratch[__float_as_int(m2.y) * NSLOT + slot], e2);
        atomicAdd(&d_scratch[__float_as_int(m3.y) * NSLOT + slot], e3);
    }

    // scalar tail
    for (int e = (P4 << 2) + gid; e < P; e += stride) {
        float x = r_scalar[3 * e + 0];
        float y = r_scalar[3 * e + 1];
        float z = r_scalar[3 * e + 2];
        float2 mi = __ldg(&((const float2*)d_qm)[idx_i[e]]);
        float qj  = __half2float(qtab[idx_j[e]]);
        float ev  = edge_energy(x, y, z, mi.x, qj);
        atomicAdd(&d_scratch[__float_as_int(mi.y) * NSLOT + slot], ev);
    }
}

// fold scratch rows into out: one warp per bin, coalesced row read
__global__ __launch_bounds__(256)
void combine_kernel(float* __restrict__ out, int M) {
    int warp = (blockIdx.x * blockDim.x + threadIdx.x) >> 5;
    int lane = threadIdx.x & 31;
    if (warp < M) {
        float s = d_scratch[warp * NSLOT + lane] + d_scratch[warp * NSLOT + 32 + lane];
        #pragma unroll
        for (int off = 16; off > 0; off >>= 1)
            s += __shfl_down_sync(0xffffffffu, s, off);
        if (lane == 0) out[warp] += s;
    }
}

// fallback for shapes outside the smem-table design
__global__ __launch_bounds__(256)
void energy_fallback(const float* __restrict__ r_scalar,
                     const float* __restrict__ q,
                     const int*   __restrict__ idx_i,
                     const int*   __restrict__ idx_j,
                     const int*   __restrict__ idx_m,
                     int P, float* __restrict__ out) {
    int gid    = blockIdx.x * blockDim.x + threadIdx.x;
    int stride = gridDim.x * blockDim.x;
    for (int e = gid; e < P; e += stride) {
        float x = r_scalar[3 * e + 0];
        float y = r_scalar[3 * e + 1];
        float z = r_scalar[3 * e + 2];
        int i = idx_i[e];
        float ev = edge_energy(x, y, z, q[i], q[idx_j[e]]);
        atomicAdd(&out[idx_m[i]], ev);
    }
}

__global__ void zero_out(float* __restrict__ out, int M) {
    int i = blockIdx.x * blockDim.x + threadIdx.x;
    if (i < M) out[i] = 0.0f;
}

extern "C" void kernel_launch(void* const* d_in, const int* in_sizes, int n_in,
                              void* d_out, int out_size) {
    // metadata order: atomic_numbers, q, r_ij, idx_i, idx_j, idx_m, maxm
    const float* q     = (const float*)d_in[1];
    const float* r_ij  = (const float*)d_in[2];
    const int*   idx_i = (const int*)d_in[3];
    const int*   idx_j = (const int*)d_in[4];
    const int*   idx_m = (const int*)d_in[5];
    int N = in_sizes[1];
    int P = in_sizes[3];
    int M = out_size;
    float* out = (float*)d_out;

    if (N > MAX_N || M > MAX_M) {
        zero_out<<<(M + 255) / 256, 256>>>(out, M);
        energy_fallback<<<1184, 256>>>(r_ij, q, idx_i, idx_j, idx_m, P, out);
        return;
    }

    prep_kernel<<<1024, 256>>>(q, idx_m, N, out, M);

    int sm_count = 148;
    cudaDeviceGetAttribute(&sm_count, cudaDevAttrMultiProcessorCount, 0);

    size_t smem_bytes = (size_t)2 * (size_t)N;   // fp16 q table (200KB for N=102400)
    cudaFuncSetAttribute(energy_kernel, cudaFuncAttributeMaxDynamicSharedMemorySize,
                         (int)smem_bytes);

    energy_kernel<<<sm_count, 1024, smem_bytes>>>(
        (const float4*)r_ij, q, (const int4*)idx_i, (const int4*)idx_j,
        r_ij, idx_i, idx_j, N, P);

    combine_kernel<<<(M * 32 + 255) / 256, 256>>>(out, M);
}

// round 4
// speedup vs baseline: 1.1114x; 1.1114x over previous
#include <cuda_runtime.h>
#include <cuda_fp16.h>
#include <cuda_bf16.h>

// ---- physical constants (double-precision derived, matching reference) ----
#define KEHALF      7.199822675975274f
#define CUTON_F     2.5f
#define CUTOFF_F    7.5f
#define LRCUT_F     10.0f
#define CUTON16_F   2328306.4365386963f
#define CUT_RCONST  0.009999999997526174f
#define CUT_CONST   0.19999999999608f
#define INV_RANGE   0.2f
#define INV_LR2     0.01f
#define TWO_OVER_LR 0.2f

#define MAX_N 102400
#define MAX_M 2048
#define NSLOT 64

// i-side packed table: (q[i] fp32, idx_m[i]) -> ONE 8B gather per edge (L1tex)
__device__ float2 d_qm[MAX_N];
// slot-strided scratch for the REDG share of the reduction
__device__ float  d_scratch[MAX_M * NSLOT];

__global__ void prep_kernel(const float* __restrict__ q,
                            const int* __restrict__ idx_m,
                            int N, float* __restrict__ out, int M) {
    int stride = gridDim.x * blockDim.x;
    int tid = blockIdx.x * blockDim.x + threadIdx.x;
    for (int i = tid; i < N; i += stride)
        d_qm[i] = make_float2(q[i], __int_as_float(idx_m[i]));
    for (int i = tid; i < M; i += stride)
        out[i] = 0.0f;
    for (int i = tid; i < MAX_M * NSLOT; i += stride)
        d_scratch[i] = 0.0f;
}

__device__ __forceinline__ float edge_energy(float x, float y, float z,
                                             float qi, float qj) {
    float s  = fmaf(x, x, fmaf(y, y, z * z));   // d^2
    float rd = rsqrtf(s);                       // 1/d
    float d  = s * rd;                          // d
    float fac = KEHALF * qi * qj;

    float f;
    if (d >= CUTOFF_F) {
        f = 0.0f;
    } else if (d <= CUTON_F) {
        f = 1.0f;
    } else {
        float t = (CUTOFF_F - d) * INV_RANGE;
        float g = __fdividef(1.0f, t) - __fdividef(1.0f, 1.0f - t);
        f = __fdividef(1.0f, 1.0f + __expf(g));
    }

    float d4  = s * s;
    float d8  = d4 * d4;
    float d16 = d8 * d8;
    float p   = exp2f(-0.0625f * __log2f(d16 + CUTON16_F));

    float omf    = 1.0f - f;
    float damped = fmaf(omf * CUT_RCONST, d, p - CUT_CONST);
    float coul   = (d < LRCUT_F) ? (rd + fmaf(d, INV_LR2, -TWO_OVER_LR)) : 0.0f;
    return fac * fmaf(f, damped, omf * coul);
}

// Pipe budget per SM (44.3K edges):
//   L1tex/LSU: streams 7K + i-gather 44K + (1/4 warps) REDG ~22K  = ~73K cyc
//   smem     : (3/4 warps) ATOMS 66K + random LDS 6K + staging 4K = ~76K cyc
__global__ __launch_bounds__(1024, 1)
void energy_kernel(const float4* __restrict__ r4,
                   const float*  __restrict__ q,
                   const int4*   __restrict__ ii4,
                   const int4*   __restrict__ jj4,
                   const float*  __restrict__ r_scalar,
                   const int*    __restrict__ idx_i,
                   const int*    __restrict__ idx_j,
                   int N, int P, float* __restrict__ out, int M) {
    extern __shared__ char sraw[];
    float*  ymol = (float*)sraw;                 // [M] fp32 accumulators
    __half* qtab = (__half*)(sraw + 4 * MAX_M);  // [N] fp16 j-side q table

    // stage q -> fp16 shared table (vectorized, coalesced) and zero ymol
    const float2* q2  = (const float2*)q;
    __half2*      qt2 = (__half2*)qtab;
    for (int i = threadIdx.x; i < (N >> 1); i += blockDim.x)
        qt2[i] = __float22half2_rn(q2[i]);
    if ((N & 1) && threadIdx.x == 0)
        qtab[N - 1] = __float2half_rn(q[N - 1]);
    for (int b = threadIdx.x; b < M; b += blockDim.x) ymol[b] = 0.0f;
    __syncthreads();

    int wid_in_blk = threadIdx.x >> 5;
    int gwarp      = blockIdx.x * (blockDim.x >> 5) + wid_in_blk;
    bool use_red   = (wid_in_blk & 3) == 3;      // 1 of 4 warps -> REDG scratch
    int slot       = gwarp & (NSLOT - 1);

    int gid    = blockIdx.x * blockDim.x + threadIdx.x;
    int stride = gridDim.x * blockDim.x;
    int P4 = P >> 2;

    for (int g = gid; g < P4; g += stride) {
        // coalesced streams, evict-first (one-pass; keep d_qm hot in L2)
        float4 a = __ldcs(&r4[3 * g + 0]);
        float4 b = __ldcs(&r4[3 * g + 1]);
        float4 c = __ldcs(&r4[3 * g + 2]);
        int4 ii = __ldcs(&ii4[g]);
        int4 jj = __ldcs(&jj4[g]);

        // i-side: 4 independent 8B gathers (L1tex) -> MLP
        float2 m0 = __ldg(&((const float2*)d_qm)[ii.x]);
        float2 m1 = __ldg(&((const float2*)d_qm)[ii.y]);
        float2 m2 = __ldg(&((const float2*)d_qm)[ii.z]);
        float2 m3 = __ldg(&((const float2*)d_qm)[ii.w]);
        // j-side: shared-memory crossbar (fp16)
        float qj0 = __half2float(qtab[jj.x]);
        float qj1 = __half2float(qtab[jj.y]);
        float qj2 = __half2float(qtab[jj.z]);
        float qj3 = __half2float(qtab[jj.w]);

        float e0 = edge_energy(a.x, a.y, a.z, m0.x, qj0);
        float e1 = edge_energy(a.w, b.x, b.y, m1.x, qj1);
        float e2 = edge_energy(b.z, b.w, c.x, m2.x, qj2);
        float e3 = edge_energy(c.y, c.z, c.w, m3.x, qj3);

        if (use_red) {
            // fire-and-forget RED into strided scratch (no return, no blocking)
            atomicAdd(&d_scratch[__float_as_int(m0.y) * NSLOT + slot], e0);
            atomicAdd(&d_scratch[__float_as_int(m1.y) * NSLOT + slot], e1);
            atomicAdd(&d_scratch[__float_as_int(m2.y) * NSLOT + slot], e2);
            atomicAdd(&d_scratch[__float_as_int(m3.y) * NSLOT + slot], e3);
        } else {
            atomicAdd(&ymol[__float_as_int(m0.y)], e0);
            atomicAdd(&ymol[__float_as_int(m1.y)], e1);
            atomicAdd(&ymol[__float_as_int(m2.y)], e2);
            atomicAdd(&ymol[__float_as_int(m3.y)], e3);
        }
    }

    // scalar tail
    for (int e = (P4 << 2) + gid; e < P; e += stride) {
        float x = r_scalar[3 * e + 0];
        float y = r_scalar[3 * e + 1];
        float z = r_scalar[3 * e + 2];
        float2 mi = __ldg(&((const float2*)d_qm)[idx_i[e]]);
        float qj  = __half2float(qtab[idx_j[e]]);
        float ev  = edge_energy(x, y, z, mi.x, qj);
        atomicAdd(&d_scratch[__float_as_int(mi.y) * NSLOT + slot], ev);
    }

    // flush block-local bins
    __syncthreads();
    for (int b = threadIdx.x; b < M; b += blockDim.x) {
        float v = ymol[b];
        if (v != 0.0f) atomicAdd(&out[b], v);
    }
}

// fold scratch rows into out: one warp per bin, coalesced row read
__global__ __launch_bounds__(256)
void combine_kernel(float* __restrict__ out, int M) {
    int warp = (blockIdx.x * blockDim.x + threadIdx.x) >> 5;
    int lane = threadIdx.x & 31;
    if (warp < M) {
        float s = d_scratch[warp * NSLOT + lane] + d_scratch[warp * NSLOT + 32 + lane];
        #pragma unroll
        for (int off = 16; off > 0; off >>= 1)
            s += __shfl_down_sync(0xffffffffu, s, off);
        if (lane == 0) out[warp] += s;
    }
}

// fallback for shapes outside the smem-table design
__global__ __launch_bounds__(256)
void energy_fallback(const float* __restrict__ r_scalar,
                     const float* __restrict__ q,
                     const int*   __restrict__ idx_i,
                     const int*   __restrict__ idx_j,
                     const int*   __restrict__ idx_m,
                     int P, float* __restrict__ out) {
    int gid    = blockIdx.x * blockDim.x + threadIdx.x;
    int stride = gridDim.x * blockDim.x;
    for (int e = gid; e < P; e += stride) {
        float x = r_scalar[3 * e + 0];
        float y = r_scalar[3 * e + 1];
        float z = r_scalar[3 * e + 2];
        int i = idx_i[e];
        float ev = edge_energy(x, y, z, q[i], q[idx_j[e]]);
        atomicAdd(&out[idx_m[i]], ev);
    }
}

__global__ void zero_out(float* __restrict__ out, int M) {
    int i = blockIdx.x * blockDim.x + threadIdx.x;
    if (i < M) out[i] = 0.0f;
}

extern "C" void kernel_launch(void* const* d_in, const int* in_sizes, int n_in,
                              void* d_out, int out_size) {
    // metadata order: atomic_numbers, q, r_ij, idx_i, idx_j, idx_m, maxm
    const float* q     = (const float*)d_in[1];
    const float* r_ij  = (const float*)d_in[2];
    const int*   idx_i = (const int*)d_in[3];
    const int*   idx_j = (const int*)d_in[4];
    const int*   idx_m = (const int*)d_in[5];
    int N = in_sizes[1];
    int P = in_sizes[3];
    int M = out_size;
    float* out = (float*)d_out;

    if (N > MAX_N || M > MAX_M) {
        zero_out<<<(M + 255) / 256, 256>>>(out, M);
        energy_fallback<<<1184, 256>>>(r_ij, q, idx_i, idx_j, idx_m, P, out);
        return;
    }

    prep_kernel<<<2048, 256>>>(q, idx_m, N, out, M);

    int sm_count = 148;
    cudaDeviceGetAttribute(&sm_count, cudaDevAttrMultiProcessorCount, 0);

    // dynamic smem: ymol (fp32, MAX_M) + fp16 q table (N)
    size_t smem_bytes = (size_t)4 * MAX_M + (size_t)2 * N;  // 8KB + 200KB
    cudaFuncSetAttribute(energy_kernel, cudaFuncAttributeMaxDynamicSharedMemorySize,
                         (int)smem_bytes);

    energy_kernel<<<sm_count, 1024, smem_bytes>>>(
        (const float4*)r_ij, q, (const int4*)idx_i, (const int4*)idx_j,
        r_ij, idx_i, idx_j, N, P, out, M);

    combine_kernel<<<(M * 32 + 255) / 256, 256>>>(out, M);
}